// round 13
// baseline (speedup 1.0000x reference)
#include <cuda_runtime.h>
#include <math.h>
#include <stdint.h>

#define HIDDEN 2048
#define NH 16
#define HD 128
#define SEQ 2048
#define BATCH 2
#define MTOT (BATCH*SEQ)   /* 4096 */

// ---------------- scratch (static device memory; no allocation) ----------------
__device__ float g_xt [(size_t)MTOT * HIDDEN];
__device__ float g_tw [(size_t)3 * HIDDEN * HIDDEN];
__device__ float g_two[(size_t)HIDDEN * HIDDEN];
__device__ float g_q  [(size_t)MTOT * HIDDEN];
__device__ float g_k  [(size_t)MTOT * HIDDEN];
__device__ float g_v  [(size_t)MTOT * HIDDEN];
__device__ float g_vt [(size_t)MTOT * HIDDEN];
__device__ float g_a  [(size_t)MTOT * HIDDEN];

__device__ __forceinline__ uint32_t f2tf(float x) {
    uint32_t y;
    asm("cvt.rna.tf32.f32 %0, %1;" : "=r"(y) : "f"(x));
    return y;
}

#define LDSM4(R0,R1,R2,R3,ADDR) \
    asm volatile("ldmatrix.sync.aligned.m8n8.x4.shared.b16 {%0,%1,%2,%3}, [%4];" \
                 : "=r"(R0),"=r"(R1),"=r"(R2),"=r"(R3) : "r"(ADDR))

#define MMA_TF32(C0,C1,C2,C3,A0,A1,A2,A3,B0,B1) \
    asm volatile("mma.sync.aligned.m16n8k8.row.col.f32.tf32.tf32.f32 " \
                 "{%0,%1,%2,%3},{%4,%5,%6,%7},{%8,%9},{%0,%1,%2,%3};" \
                 : "+f"(C0),"+f"(C1),"+f"(C2),"+f"(C3) \
                 : "r"(A0),"r"(A1),"r"(A2),"r"(A3),"r"(B0),"r"(B1))

#define CP_ASYNC16(SA, GA) \
    asm volatile("cp.async.cg.shared.global [%0], [%1], 16;" :: "r"(SA), "l"(GA))
#define CP_COMMIT() asm volatile("cp.async.commit_group;")
#define BARN(ID, CNT) asm volatile("bar.sync %0, %1;" :: "r"(ID), "r"(CNT) : "memory")

// =======================================================================
// Single-pass tf32 rounding of x, wq|wk|wv (packed), wo
// =======================================================================
#define NX4 (MTOT * HIDDEN / 4)
#define NW4 (HIDDEN * HIDDEN / 4)
#define NTOT4 (NX4 + 4 * NW4)

__global__ __launch_bounds__(256)
void cvt_all(float* __restrict__ xt, const float* __restrict__ x,
             float* __restrict__ tw, const float* __restrict__ wq,
             const float* __restrict__ wk, const float* __restrict__ wv,
             float* __restrict__ two, const float* __restrict__ wo)
{
    int i = blockIdx.x * blockDim.x + threadIdx.x;
    int stride = gridDim.x * blockDim.x;
    for (; i < NTOT4; i += stride) {
        const float4* sp;
        uint4* dp;
        if (i < NX4) {
            sp = (const float4*)x + i;            dp = (uint4*)xt + i;
        } else {
            int j = i - NX4;
            int w = j / NW4, off = j - w * NW4;
            if      (w == 0) { sp = (const float4*)wq + off; dp = (uint4*)tw + off; }
            else if (w == 1) { sp = (const float4*)wk + off; dp = (uint4*)(tw + (size_t)HIDDEN*HIDDEN) + off; }
            else if (w == 2) { sp = (const float4*)wv + off; dp = (uint4*)(tw + (size_t)2*HIDDEN*HIDDEN) + off; }
            else             { sp = (const float4*)wo + off; dp = (uint4*)two + off; }
        }
        float4 v = *sp;
        *dp = make_uint4(f2tf(v.x), f2tf(v.y), f2tf(v.z), f2tf(v.w));
    }
}

// =======================================================================
// cp.async 3-stage tf32 GEMM (NT), BM=128, BN=128, BK=32, 256 threads
// + L2-friendly CTA swizzle (unchanged from R12 — protected win).
// =======================================================================
#define STAGES 3
#define STG_U32 8192
#define GEMM_SMEM (STAGES*STG_U32*4)

__global__ __launch_bounds__(256)
void gemm_cp(const float* __restrict__ A, const float* __restrict__ W,
             const float* __restrict__ b0, const float* __restrict__ b1,
             const float* __restrict__ b2,
             float* __restrict__ C0, float* __restrict__ C1, float* __restrict__ C2,
             int M, int N, int K, int mode)
{
    extern __shared__ uint32_t smem_u[];
    const int tid  = threadIdx.x;
    const int lane = tid & 31;
    const int wid  = tid >> 5;
    const int warp_m = wid >> 2;
    const int warp_n = wid & 3;

    int bid   = blockIdx.y * gridDim.x + blockIdx.x;
    int chunk = gridDim.x * 8;
    int cid   = bid / chunk;
    int rem   = bid - cid * chunk;
    int by    = cid * 8 + (rem & 7);
    int bx    = rem >> 3;
    const int m0 = by * 128;
    const int n0 = bx * 128;

    const int mat = lane >> 3, r = lane & 7;
    const int a_sh = mat >> 1, a_roff = r + ((mat & 1) << 3);
    const int b_sh = mat & 1,  b_roff = r + ((mat >> 1) << 3);

    const int grow = tid >> 3;
    const int gseg = tid & 7;
    const int sseg = gseg ^ (grow & 7);

    const uint32_t sbase = (uint32_t)__cvta_generic_to_shared(smem_u);

    uint32_t sa[4], sb[4];
#pragma unroll
    for (int l = 0; l < 4; l++) {
        sa[l] = sbase + (uint32_t)((grow + 32 * l) * 32 + sseg * 4) * 4u;
        sb[l] = sa[l] + 16384u;
    }

    uint32_t rowbA[4], rowbB[2];
#pragma unroll
    for (int mf = 0; mf < 4; mf++)
        rowbA[mf] = (uint32_t)(warp_m * 64 + mf * 16 + a_roff) * 128u;
#pragma unroll
    for (int pb = 0; pb < 2; pb++)
        rowbB[pb] = (uint32_t)(warp_n * 32 + pb * 16 + b_roff) * 128u + 16384u;

    float acc[4][4][4];
#pragma unroll
    for (int i = 0; i < 4; i++)
#pragma unroll
        for (int j = 0; j < 4; j++)
#pragma unroll
            for (int c = 0; c < 4; c++) acc[i][j][c] = 0.f;

    const int KT = K >> 5;

#pragma unroll
    for (int s = 0; s < STAGES - 1; s++) {
        int k0 = s * 32;
        uint32_t soff = (uint32_t)s * 32768u;
#pragma unroll
        for (int l = 0; l < 4; l++) {
            int row = grow + 32 * l;
            CP_ASYNC16(sa[l] + soff, (const void*)(A + (size_t)(m0 + row) * K + k0 + gseg * 4));
            CP_ASYNC16(sb[l] + soff, (const void*)(W + (size_t)(n0 + row) * K + k0 + gseg * 4));
        }
        CP_COMMIT();
    }

    int stage = 0;
    for (int kt = 0; kt < KT; kt++) {
        asm volatile("cp.async.wait_group 1;");
        __syncthreads();

        const uint32_t abase = sbase + (uint32_t)stage * 32768u;
#pragma unroll
        for (int ks = 0; ks < 4; ks++) {
            uint32_t af[4][4];
            uint32_t bf[4][2];
#pragma unroll
            for (int mf = 0; mf < 4; mf++) {
                uint32_t addr = abase + rowbA[mf] + (uint32_t)((((ks << 1) + a_sh) ^ r) << 4);
                LDSM4(af[mf][0], af[mf][1], af[mf][2], af[mf][3], addr);
            }
#pragma unroll
            for (int pb = 0; pb < 2; pb++) {
                uint32_t addr = abase + rowbB[pb] + (uint32_t)((((ks << 1) + b_sh) ^ r) << 4);
                uint32_t t0, t1, t2, t3;
                LDSM4(t0, t1, t2, t3, addr);
                bf[pb * 2 + 0][0] = t0; bf[pb * 2 + 0][1] = t1;
                bf[pb * 2 + 1][0] = t2; bf[pb * 2 + 1][1] = t3;
            }
#pragma unroll
            for (int mf = 0; mf < 4; mf++)
#pragma unroll
                for (int nf = 0; nf < 4; nf++)
                    MMA_TF32(acc[mf][nf][0], acc[mf][nf][1], acc[mf][nf][2], acc[mf][nf][3],
                             af[mf][0], af[mf][1], af[mf][2], af[mf][3],
                             bf[nf][0], bf[nf][1]);
        }

        int kn = kt + STAGES - 1;
        if (kn < KT) {
            int k0 = kn * 32;
            uint32_t soff = (uint32_t)(kn % STAGES) * 32768u;
#pragma unroll
            for (int l = 0; l < 4; l++) {
                int row = grow + 32 * l;
                CP_ASYNC16(sa[l] + soff, (const void*)(A + (size_t)(m0 + row) * K + k0 + gseg * 4));
                CP_ASYNC16(sb[l] + soff, (const void*)(W + (size_t)(n0 + row) * K + k0 + gseg * 4));
            }
        }
        CP_COMMIT();
        stage = (stage + 1 == STAGES) ? 0 : stage + 1;
    }

    const int group = lane >> 2;
    const int tcol  = lane & 3;
    const int which = n0 >> 11;
    const float* bp = (which == 0) ? b0 : (which == 1) ? b1 : b2;
    float* Cw = (which == 0) ? C0 : (which == 1) ? C1 : C2;

#pragma unroll
    for (int mf = 0; mf < 4; mf++) {
#pragma unroll
        for (int nf = 0; nf < 4; nf++) {
            int col = n0 + warp_n * 32 + nf * 8 + tcol * 2;
            int colr = col & 2047;
            float bb0, bb1;
            if (mode) { bb0 = bp[colr]; bb1 = bp[colr + 1]; }
            else      { bb0 = b0[col];  bb1 = b0[col + 1]; }
            int mrow0 = m0 + warp_m * 64 + mf * 16 + group;
#pragma unroll
            for (int half = 0; half < 2; half++) {
                int mrow = mrow0 + half * 8;
                float v0 = acc[mf][nf][half * 2 + 0] + bb0;
                float v1 = acc[mf][nf][half * 2 + 1] + bb1;
                if (!mode) {
                    *(float2*)(C0 + (size_t)mrow * N + col) = make_float2(v0, v1);
                } else {
                    int b = mrow >> 11;
                    int s = mrow & 2047;
                    int h = colr >> 7;
                    int d = colr & 127;
                    uint2 u = make_uint2(f2tf(v0), f2tf(v1));
                    *(uint2*)(Cw + (((size_t)((b << 4) + h) * SEQ + s) << 7) + d) = u;
                }
            }
        }
    }
}

// =======================================================================
// V transpose: [bh][s][d] -> [bh][d][s]
// =======================================================================
__global__ __launch_bounds__(256)
void transpose_v(const float* __restrict__ in, float* __restrict__ out)
{
    __shared__ float t[32][33];
    const int bh = blockIdx.z;
    const int d0 = blockIdx.x * 32;
    const int s0 = blockIdx.y * 32;
    const float* ip = in  + (size_t)bh * SEQ * HD;
    float*       op = out + (size_t)bh * HD * SEQ;
    const int tx = threadIdx.x & 31;
    const int ty = threadIdx.x >> 5;
#pragma unroll
    for (int j = 0; j < 32; j += 8)
        t[ty + j][tx] = ip[(size_t)(s0 + ty + j) * HD + d0 + tx];
    __syncthreads();
#pragma unroll
    for (int j = 0; j < 32; j += 8)
        op[(size_t)(d0 + ty + j) * SEQ + s0 + tx] = t[tx][ty + j];
}

// =======================================================================
// tf32 flash attention, Br=128, Bc=64, 512 threads.
// Group-scoped pipeline: warp_n group n (256 threads) loads/consumes its
// own K-rows [n*32,+32) and V-rows [n*64,+64); softmax/P sync via 64-thread
// pair barriers (warps (m,0)/(m,1)). No CTA-wide barriers in the loop.
// Smem u32: Q[16384] K0[8192] K1[8192] V[8192] P[8192] red[512]
// =======================================================================
#define FQ   0
#define FK0  16384
#define FV   32768
#define FP   40960
#define FRED 49152
#define FLASH_SMEM ((49152 + 512) * 4)   /* 198656 B */

__global__ __launch_bounds__(512)
void flash_tf32(const float* __restrict__ Q, const float* __restrict__ K,
                const float* __restrict__ Vt, float* __restrict__ Out)
{
    extern __shared__ uint32_t sm[];
    float2* redp = (float2*)(sm + FRED);

    const int tid  = threadIdx.x;
    const int lane = tid & 31;
    const int wid  = tid >> 5;
    const int warp_m = wid & 7;          // 8 row groups of 16
    const int warp_n = wid >> 3;         // 2 col groups (= tid>>8)
    const int qb = (gridDim.x - 1) - blockIdx.x;
    const int bh = blockIdx.y;
    const int g    = lane >> 2;
    const int tcol = lane & 3;
    const float scale = 0.08838834764831845f;

    const float* Qg = Q  + ((size_t)bh * SEQ + qb * 128) * HD;
    const float* Kg = K  + (size_t)bh * SEQ * HD;
    const float* Vg = Vt + (size_t)bh * HD * SEQ;

    const uint32_t sbase = (uint32_t)__cvta_generic_to_shared(sm);
    const int mat = lane >> 3, r = lane & 7;
    const int a_sh = mat >> 1, a_roff = r + ((mat & 1) << 3);
    const int b_sh = mat & 1,  b_roff = r + ((mat >> 1) << 3);

    const uint32_t qa_base = sbase + (uint32_t)(warp_m * 16 + a_roff) * 512u;
    uint32_t kb_row[2];
#pragma unroll
    for (int pb = 0; pb < 2; pb++)
        kb_row[pb] = sbase + FK0 * 4 + (uint32_t)(warp_n * 32 + pb * 16 + b_roff) * 512u;
    const uint32_t pa_base = sbase + FP * 4 + (uint32_t)(warp_m * 16 + a_roff) * 256u;
    uint32_t vb_row[4];
#pragma unroll
    for (int pb = 0; pb < 4; pb++)
        vb_row[pb] = sbase + FV * 4 + (uint32_t)(warp_n * 64 + pb * 16 + b_roff) * 256u;

    // ---- group-local cp.async addressing ----
    const int grp = tid >> 8;            // == warp_n
    const int gt  = tid & 255;
    const int GBAR = 9 + grp;            // group barrier id (256 threads)
    const int PBAR = 1 + warp_m;         // pair barrier id (64 threads)

    // K: group loads rows [grp*32, +32), 128 floats each (32 x 16B segs)
    const int krow_g = grp * 32 + (gt >> 3);     // fixed row for this thread
    const int kseg0  = gt & 7;                   // + 8*l, l<4
    uint32_t kdst[4];
#pragma unroll
    for (int l = 0; l < 4; l++)
        kdst[l] = sbase + (uint32_t)(FK0 + krow_g * 128 + ((kseg0 + 8 * l) ^ (krow_g & 7)) * 4) * 4u;

    // V: group loads d-rows [grp*64, +64), 64 floats each (16 x 16B segs)
    const int vd_g  = grp * 64 + (gt >> 2);
    const int vseg0 = gt & 3;                    // + 4*l, l<4
    uint32_t vdst[4];
#pragma unroll
    for (int l = 0; l < 4; l++)
        vdst[l] = sbase + (uint32_t)(FV + vd_g * 64 + ((vseg0 + 4 * l) ^ (vd_g & 7)) * 4) * 4u;

    // ---- Q tile 128x128: raw tf32 bits, swizzled (full CTA) ----
#pragma unroll
    for (int l = 0; l < 8; l++) {
        int idx = tid + l * 512;
        int row = idx >> 5;
        int seg = idx & 31;
        uint4 u = *(const uint4*)&Qg[row * HD + seg * 4];
        *(uint4*)(sm + row * 128 + (seg ^ (row & 7)) * 4) = u;
    }

    // prologue: prefetch K[0] (own group half)
#pragma unroll
    for (int l = 0; l < 4; l++)
        CP_ASYNC16(kdst[l], (const void*)(Kg + (size_t)krow_g * HD + (kseg0 + 8 * l) * 4));
    CP_COMMIT();

    __syncthreads();   // Q visible to all (only CTA-wide barrier)

    float o[8][4];
#pragma unroll
    for (int nf = 0; nf < 8; nf++)
#pragma unroll
        for (int c = 0; c < 4; c++) o[nf][c] = 0.f;
    float mrow[2] = {-1e30f, -1e30f};
    float lrow[2] = {0.f, 0.f};

    const int nkb = 2 * qb + 2;
    for (int kb = 0; kb < nkb; kb++) {
        const uint32_t kcur = (kb & 1) ? 32768u : 0u;

        // K[kb] landed for this group; group done with old V/P/K buffers
        asm volatile("cp.async.wait_group 0;");
        BARN(GBAR, 256);

        // issue V[kb] (own half) then K[kb+1] (own half)
#pragma unroll
        for (int l = 0; l < 4; l++)
            CP_ASYNC16(vdst[l], (const void*)(Vg + (size_t)vd_g * SEQ + kb * 64 + (vseg0 + 4 * l) * 4));
        CP_COMMIT();
        if (kb + 1 < nkb) {
            uint32_t koff = (kb & 1) ? 0u : 32768u;
#pragma unroll
            for (int l = 0; l < 4; l++)
                CP_ASYNC16(kdst[l] + koff,
                           (const void*)(Kg + (size_t)((kb + 1) * 64 + krow_g) * HD + (kseg0 + 8 * l) * 4));
        }
        CP_COMMIT();

        // ---- scores ----
        float s[4][4];
#pragma unroll
        for (int nf = 0; nf < 4; nf++)
#pragma unroll
            for (int c = 0; c < 4; c++) s[nf][c] = 0.f;

#pragma unroll
        for (int ks = 0; ks < 16; ks++) {
            uint32_t a0, a1, a2, a3;
            LDSM4(a0, a1, a2, a3, qa_base + (uint32_t)((((ks << 1) + a_sh) ^ r) << 4));
            uint32_t bf[4][2];
#pragma unroll
            for (int pb = 0; pb < 2; pb++) {
                uint32_t t0, t1, t2, t3;
                LDSM4(t0, t1, t2, t3, kb_row[pb] + kcur + (uint32_t)((((ks << 1) + b_sh) ^ r) << 4));
                bf[pb * 2 + 0][0] = t0; bf[pb * 2 + 0][1] = t1;
                bf[pb * 2 + 1][0] = t2; bf[pb * 2 + 1][1] = t3;
            }
#pragma unroll
            for (int nf = 0; nf < 4; nf++)
                MMA_TF32(s[nf][0], s[nf][1], s[nf][2], s[nf][3],
                         a0, a1, a2, a3, bf[nf][0], bf[nf][1]);
        }

        // ---- scale + causal mask ----
#pragma unroll
        for (int nf = 0; nf < 4; nf++)
#pragma unroll
            for (int c = 0; c < 4; c++) s[nf][c] *= scale;
        if (kb >= 2 * qb) {
#pragma unroll
            for (int nf = 0; nf < 4; nf++)
#pragma unroll
                for (int c = 0; c < 4; c++) {
                    int lr = warp_m * 16 + g + (c >> 1) * 8;
                    int lc = warp_n * 32 + nf * 8 + 2 * tcol + (c & 1);
                    if (kb * 64 + lc > qb * 128 + lr) s[nf][c] = -1e30f;
                }
        }

        // ---- softmax: local partials -> pair exchange ----
        float p[2][8], mxw[2];
#pragma unroll
        for (int h = 0; h < 2; h++) {
            float mx = s[0][h * 2];
#pragma unroll
            for (int nf = 0; nf < 4; nf++) {
                mx = fmaxf(mx, s[nf][h * 2 + 0]);
                mx = fmaxf(mx, s[nf][h * 2 + 1]);
            }
            mx = fmaxf(mx, __shfl_xor_sync(0xffffffffu, mx, 1));
            mx = fmaxf(mx, __shfl_xor_sync(0xffffffffu, mx, 2));
            float sum = 0.f;
#pragma unroll
            for (int nf = 0; nf < 4; nf++) {
                float p0 = __expf(s[nf][h * 2 + 0] - mx);
                float p1 = __expf(s[nf][h * 2 + 1] - mx);
                p[h][nf * 2 + 0] = p0;
                p[h][nf * 2 + 1] = p1;
                sum += p0 + p1;
            }
            sum += __shfl_xor_sync(0xffffffffu, sum, 1);
            sum += __shfl_xor_sync(0xffffffffu, sum, 2);
            mxw[h] = mx;
            if (tcol == 0)
                redp[(warp_m * 16 + g + h * 8) * 2 + warp_n] = make_float2(mx, sum);
        }
        BARN(PBAR, 64);   // pair exchange visible

#pragma unroll
        for (int h = 0; h < 2; h++) {
            int row = warp_m * 16 + g + h * 8;
            float2 e0 = redp[row * 2 + 0];
            float2 e1 = redp[row * 2 + 1];
            float mnew  = fmaxf(mrow[h], fmaxf(e0.x, e1.x));
            float alpha = __expf(mrow[h] - mnew);
            lrow[h] = lrow[h] * alpha + e0.y * __expf(e0.x - mnew)
                                      + e1.y * __expf(e1.x - mnew);
            mrow[h] = mnew;
            float fac = __expf(mxw[h] - mnew);
#pragma unroll
            for (int nf = 0; nf < 4; nf++) {
                int col = warp_n * 32 + nf * 8 + 2 * tcol;
                uint32_t w = FP + row * 64 + ((col >> 2) ^ (row & 7)) * 4 + (col & 3);
                uint2 u = make_uint2(f2tf(p[h][nf * 2 + 0] * fac),
                                     f2tf(p[h][nf * 2 + 1] * fac));
                *(uint2*)(sm + w) = u;
            }
#pragma unroll
            for (int nfo = 0; nfo < 8; nfo++) {
                o[nfo][h * 2 + 0] *= alpha;
                o[nfo][h * 2 + 1] *= alpha;
            }
        }
        BARN(PBAR, 64);   // P tile visible within pair

        asm volatile("cp.async.wait_group 1;");   // V[kb] landed (own group)
        BARN(GBAR, 256);                          // V half visible to group

        // ---- PV ----
#pragma unroll
        for (int ks = 0; ks < 8; ks++) {
            uint32_t a0, a1, a2, a3;
            LDSM4(a0, a1, a2, a3, pa_base + (uint32_t)((((ks << 1) + a_sh) ^ r) << 4));
            uint32_t bf[8][2];
#pragma unroll
            for (int pb = 0; pb < 4; pb++) {
                uint32_t t0, t1, t2, t3;
                LDSM4(t0, t1, t2, t3, vb_row[pb] + (uint32_t)((((ks << 1) + b_sh) ^ r) << 4));
                bf[pb * 2 + 0][0] = t0; bf[pb * 2 + 0][1] = t1;
                bf[pb * 2 + 1][0] = t2; bf[pb * 2 + 1][1] = t3;
            }
#pragma unroll
            for (int nf = 0; nf < 8; nf++)
                MMA_TF32(o[nf][0], o[nf][1], o[nf][2], o[nf][3],
                         a0, a1, a2, a3, bf[nf][0], bf[nf][1]);
        }
    }

    // ---- epilogue ----
    const int b = bh >> 4;
    const int hh = bh & 15;
#pragma unroll
    for (int h = 0; h < 2; h++) {
        float inv = 1.0f / lrow[h];
        int srow = qb * 128 + warp_m * 16 + g + h * 8;
        float* op = Out + ((size_t)(b * SEQ + srow)) * HIDDEN + hh * HD;
#pragma unroll
        for (int nf = 0; nf < 8; nf++) {
            int d = warp_n * 64 + nf * 8 + 2 * tcol;
            uint2 u = make_uint2(f2tf(o[nf][h * 2 + 0] * inv),
                                 f2tf(o[nf][h * 2 + 1] * inv));
            *(uint2*)(op + d) = u;
        }
    }
}

// =======================================================================
extern "C" void kernel_launch(void* const* d_in, const int* in_sizes, int n_in,
                              void* d_out, int out_size)
{
    const float* x  = (const float*)d_in[0];
    const float* wq = (const float*)d_in[1];
    const float* bq = (const float*)d_in[2];
    const float* wk = (const float*)d_in[3];
    const float* bk = (const float*)d_in[4];
    const float* wv = (const float*)d_in[5];
    const float* bv = (const float*)d_in[6];
    const float* wo = (const float*)d_in[7];
    const float* bo = (const float*)d_in[8];
    float* out = (float*)d_out;

    float *xt, *tw, *two, *q, *k, *v, *vt, *a;
    cudaGetSymbolAddress((void**)&xt,  g_xt);
    cudaGetSymbolAddress((void**)&tw,  g_tw);
    cudaGetSymbolAddress((void**)&two, g_two);
    cudaGetSymbolAddress((void**)&q,   g_q);
    cudaGetSymbolAddress((void**)&k,   g_k);
    cudaGetSymbolAddress((void**)&v,   g_v);
    cudaGetSymbolAddress((void**)&vt,  g_vt);
    cudaGetSymbolAddress((void**)&a,   g_a);

    static int attr_done = 0;
    if (!attr_done) {
        cudaFuncSetAttribute(gemm_cp, cudaFuncAttributeMaxDynamicSharedMemorySize, GEMM_SMEM);
        cudaFuncSetAttribute(flash_tf32, cudaFuncAttributeMaxDynamicSharedMemorySize, FLASH_SMEM);
        attr_done = 1;
    }

    // tf32 pre-round (single launch)
    cvt_all<<<2048, 256>>>(xt, x, tw, wq, wk, wv, two, wo);

    // fused QKV projection: N = 6144
    gemm_cp<<<dim3(3 * HIDDEN / 128, MTOT / 128), 256, GEMM_SMEM>>>(
        xt, tw, bq, bk, bv, q, k, v, MTOT, 3 * HIDDEN, HIDDEN, 1);

    transpose_v<<<dim3(HD / 32, SEQ / 32, BATCH * NH), 256>>>(v, vt);

    flash_tf32<<<dim3(SEQ / 128, BATCH * NH), 512, FLASH_SMEM>>>(q, k, vt, a);

    // output projection (full fp32 out)
    gemm_cp<<<dim3(HIDDEN / 128, MTOT / 128), 256, GEMM_SMEM>>>(
        a, two, bo, bo, bo, out, out, out, MTOT, HIDDEN, HIDDEN, 0);
}

// round 15
// speedup vs baseline: 1.5576x; 1.5576x over previous
#include <cuda_runtime.h>
#include <math.h>
#include <stdint.h>

#define HIDDEN 2048
#define NH 16
#define HD 128
#define SEQ 2048
#define BATCH 2
#define MTOT (BATCH*SEQ)   /* 4096 */

// ---------------- scratch (static device memory; no allocation) ----------------
__device__ float g_xt [(size_t)MTOT * HIDDEN];
__device__ float g_tw [(size_t)3 * HIDDEN * HIDDEN];
__device__ float g_two[(size_t)HIDDEN * HIDDEN];
__device__ float g_q  [(size_t)MTOT * HIDDEN];
__device__ float g_k  [(size_t)MTOT * HIDDEN];
__device__ float g_v  [(size_t)MTOT * HIDDEN];
__device__ float g_vt [(size_t)MTOT * HIDDEN];
__device__ float g_a  [(size_t)MTOT * HIDDEN];

__device__ __forceinline__ uint32_t f2tf(float x) {
    uint32_t y;
    asm("cvt.rna.tf32.f32 %0, %1;" : "=r"(y) : "f"(x));
    return y;
}

#define LDSM4(R0,R1,R2,R3,ADDR) \
    asm volatile("ldmatrix.sync.aligned.m8n8.x4.shared.b16 {%0,%1,%2,%3}, [%4];" \
                 : "=r"(R0),"=r"(R1),"=r"(R2),"=r"(R3) : "r"(ADDR))

#define MMA_TF32(C0,C1,C2,C3,A0,A1,A2,A3,B0,B1) \
    asm volatile("mma.sync.aligned.m16n8k8.row.col.f32.tf32.tf32.f32 " \
                 "{%0,%1,%2,%3},{%4,%5,%6,%7},{%8,%9},{%0,%1,%2,%3};" \
                 : "+f"(C0),"+f"(C1),"+f"(C2),"+f"(C3) \
                 : "r"(A0),"r"(A1),"r"(A2),"r"(A3),"r"(B0),"r"(B1))

#define CP_ASYNC16(SA, GA) \
    asm volatile("cp.async.cg.shared.global [%0], [%1], 16;" :: "r"(SA), "l"(GA))
#define CP_COMMIT() asm volatile("cp.async.commit_group;")

// =======================================================================
// Single-pass tf32 rounding of x, wq|wk|wv (packed), wo
// =======================================================================
#define NX4 (MTOT * HIDDEN / 4)
#define NW4 (HIDDEN * HIDDEN / 4)
#define NTOT4 (NX4 + 4 * NW4)

__global__ __launch_bounds__(256)
void cvt_all(float* __restrict__ xt, const float* __restrict__ x,
             float* __restrict__ tw, const float* __restrict__ wq,
             const float* __restrict__ wk, const float* __restrict__ wv,
             float* __restrict__ two, const float* __restrict__ wo)
{
    int i = blockIdx.x * blockDim.x + threadIdx.x;
    int stride = gridDim.x * blockDim.x;
    for (; i < NTOT4; i += stride) {
        const float4* sp;
        uint4* dp;
        if (i < NX4) {
            sp = (const float4*)x + i;            dp = (uint4*)xt + i;
        } else {
            int j = i - NX4;
            int w = j / NW4, off = j - w * NW4;
            if      (w == 0) { sp = (const float4*)wq + off; dp = (uint4*)tw + off; }
            else if (w == 1) { sp = (const float4*)wk + off; dp = (uint4*)(tw + (size_t)HIDDEN*HIDDEN) + off; }
            else if (w == 2) { sp = (const float4*)wv + off; dp = (uint4*)(tw + (size_t)2*HIDDEN*HIDDEN) + off; }
            else             { sp = (const float4*)wo + off; dp = (uint4*)two + off; }
        }
        float4 v = *sp;
        *dp = make_uint4(f2tf(v.x), f2tf(v.y), f2tf(v.z), f2tf(v.w));
    }
}

// =======================================================================
// cp.async 3-stage tf32 GEMM (NT), BM=128, BN=128, BK=32, 256 threads
// + L2-friendly CTA swizzle (R12 proven).
// =======================================================================
#define STAGES 3
#define STG_U32 8192
#define GEMM_SMEM (STAGES*STG_U32*4)      /* 98304 B -> 2 CTAs/SM */

__global__ __launch_bounds__(256)
void gemm_cp(const float* __restrict__ A, const float* __restrict__ W,
             const float* __restrict__ b0, const float* __restrict__ b1,
             const float* __restrict__ b2,
             float* __restrict__ C0, float* __restrict__ C1, float* __restrict__ C2,
             int M, int N, int K, int mode)
{
    extern __shared__ uint32_t smem_u[];
    const int tid  = threadIdx.x;
    const int lane = tid & 31;
    const int wid  = tid >> 5;
    const int warp_m = wid >> 2;
    const int warp_n = wid & 3;

    int bid   = blockIdx.y * gridDim.x + blockIdx.x;
    int chunk = gridDim.x * 8;
    int cid   = bid / chunk;
    int rem   = bid - cid * chunk;
    int by    = cid * 8 + (rem & 7);
    int bx    = rem >> 3;
    const int m0 = by * 128;
    const int n0 = bx * 128;

    const int mat = lane >> 3, r = lane & 7;
    const int a_sh = mat >> 1, a_roff = r + ((mat & 1) << 3);
    const int b_sh = mat & 1,  b_roff = r + ((mat >> 1) << 3);

    const int grow = tid >> 3;
    const int gseg = tid & 7;
    const int sseg = gseg ^ (grow & 7);

    const uint32_t sbase = (uint32_t)__cvta_generic_to_shared(smem_u);

    uint32_t sa[4], sb[4];
#pragma unroll
    for (int l = 0; l < 4; l++) {
        sa[l] = sbase + (uint32_t)((grow + 32 * l) * 32 + sseg * 4) * 4u;
        sb[l] = sa[l] + 16384u;
    }

    uint32_t rowbA[4], rowbB[2];
#pragma unroll
    for (int mf = 0; mf < 4; mf++)
        rowbA[mf] = (uint32_t)(warp_m * 64 + mf * 16 + a_roff) * 128u;
#pragma unroll
    for (int pb = 0; pb < 2; pb++)
        rowbB[pb] = (uint32_t)(warp_n * 32 + pb * 16 + b_roff) * 128u + 16384u;

    float acc[4][4][4];
#pragma unroll
    for (int i = 0; i < 4; i++)
#pragma unroll
        for (int j = 0; j < 4; j++)
#pragma unroll
            for (int c = 0; c < 4; c++) acc[i][j][c] = 0.f;

    const int KT = K >> 5;

#pragma unroll
    for (int s = 0; s < STAGES - 1; s++) {
        int k0 = s * 32;
        uint32_t soff = (uint32_t)s * 32768u;
#pragma unroll
        for (int l = 0; l < 4; l++) {
            int row = grow + 32 * l;
            CP_ASYNC16(sa[l] + soff, (const void*)(A + (size_t)(m0 + row) * K + k0 + gseg * 4));
            CP_ASYNC16(sb[l] + soff, (const void*)(W + (size_t)(n0 + row) * K + k0 + gseg * 4));
        }
        CP_COMMIT();
    }

    int stage = 0;
    for (int kt = 0; kt < KT; kt++) {
        asm volatile("cp.async.wait_group 1;");
        __syncthreads();

        const uint32_t abase = sbase + (uint32_t)stage * 32768u;
#pragma unroll
        for (int ks = 0; ks < 4; ks++) {
            uint32_t af[4][4];
            uint32_t bf[4][2];
#pragma unroll
            for (int mf = 0; mf < 4; mf++) {
                uint32_t addr = abase + rowbA[mf] + (uint32_t)((((ks << 1) + a_sh) ^ r) << 4);
                LDSM4(af[mf][0], af[mf][1], af[mf][2], af[mf][3], addr);
            }
#pragma unroll
            for (int pb = 0; pb < 2; pb++) {
                uint32_t addr = abase + rowbB[pb] + (uint32_t)((((ks << 1) + b_sh) ^ r) << 4);
                uint32_t t0, t1, t2, t3;
                LDSM4(t0, t1, t2, t3, addr);
                bf[pb * 2 + 0][0] = t0; bf[pb * 2 + 0][1] = t1;
                bf[pb * 2 + 1][0] = t2; bf[pb * 2 + 1][1] = t3;
            }
#pragma unroll
            for (int mf = 0; mf < 4; mf++)
#pragma unroll
                for (int nf = 0; nf < 4; nf++)
                    MMA_TF32(acc[mf][nf][0], acc[mf][nf][1], acc[mf][nf][2], acc[mf][nf][3],
                             af[mf][0], af[mf][1], af[mf][2], af[mf][3],
                             bf[nf][0], bf[nf][1]);
        }

        int kn = kt + STAGES - 1;
        if (kn < KT) {
            int k0 = kn * 32;
            uint32_t soff = (uint32_t)(kn % STAGES) * 32768u;
#pragma unroll
            for (int l = 0; l < 4; l++) {
                int row = grow + 32 * l;
                CP_ASYNC16(sa[l] + soff, (const void*)(A + (size_t)(m0 + row) * K + k0 + gseg * 4));
                CP_ASYNC16(sb[l] + soff, (const void*)(W + (size_t)(n0 + row) * K + k0 + gseg * 4));
            }
        }
        CP_COMMIT();
        stage = (stage + 1 == STAGES) ? 0 : stage + 1;
    }

    const int group = lane >> 2;
    const int tcol  = lane & 3;
    const int which = n0 >> 11;
    const float* bp = (which == 0) ? b0 : (which == 1) ? b1 : b2;
    float* Cw = (which == 0) ? C0 : (which == 1) ? C1 : C2;

#pragma unroll
    for (int mf = 0; mf < 4; mf++) {
#pragma unroll
        for (int nf = 0; nf < 4; nf++) {
            int col = n0 + warp_n * 32 + nf * 8 + tcol * 2;
            int colr = col & 2047;
            float bb0, bb1;
            if (mode) { bb0 = bp[colr]; bb1 = bp[colr + 1]; }
            else      { bb0 = b0[col];  bb1 = b0[col + 1]; }
            int mrow0 = m0 + warp_m * 64 + mf * 16 + group;
#pragma unroll
            for (int half = 0; half < 2; half++) {
                int mrow = mrow0 + half * 8;
                float v0 = acc[mf][nf][half * 2 + 0] + bb0;
                float v1 = acc[mf][nf][half * 2 + 1] + bb1;
                if (!mode) {
                    *(float2*)(C0 + (size_t)mrow * N + col) = make_float2(v0, v1);
                } else {
                    int b = mrow >> 11;
                    int s = mrow & 2047;
                    int h = colr >> 7;
                    int d = colr & 127;
                    uint2 u = make_uint2(f2tf(v0), f2tf(v1));
                    *(uint2*)(Cw + (((size_t)((b << 4) + h) * SEQ + s) << 7) + d) = u;
                }
            }
        }
    }
}

// =======================================================================
// V transpose: [bh][s][d] -> [bh][d][s]
// =======================================================================
__global__ __launch_bounds__(256)
void transpose_v(const float* __restrict__ in, float* __restrict__ out)
{
    __shared__ float t[32][33];
    const int bh = blockIdx.z;
    const int d0 = blockIdx.x * 32;
    const int s0 = blockIdx.y * 32;
    const float* ip = in  + (size_t)bh * SEQ * HD;
    float*       op = out + (size_t)bh * HD * SEQ;
    const int tx = threadIdx.x & 31;
    const int ty = threadIdx.x >> 5;
#pragma unroll
    for (int j = 0; j < 32; j += 8)
        t[ty + j][tx] = ip[(size_t)(s0 + ty + j) * HD + d0 + tx];
    __syncthreads();
#pragma unroll
    for (int j = 0; j < 32; j += 8)
        op[(size_t)(d0 + ty + j) * SEQ + s0 + tx] = t[tx][ty + j];
}

// =======================================================================
// tf32 flash attention (R12 proven): Br=128, Bc=64, 512 threads,
// K double-buffered cp.async (explicit kcur add), V issued post-K-sync,
// 3 barriers/iter.
// Smem u32: Q[16384] K0[8192] K1[8192] V[8192] P[8192] red[512]
// =======================================================================
#define FQ   0
#define FK0  16384
#define FV   32768
#define FP   40960
#define FRED 49152
#define FLASH_SMEM ((49152 + 512) * 4)   /* 198656 B */

__global__ __launch_bounds__(512)
void flash_tf32(const float* __restrict__ Q, const float* __restrict__ K,
                const float* __restrict__ Vt, float* __restrict__ Out)
{
    extern __shared__ uint32_t sm[];
    float2* redp = (float2*)(sm + FRED);

    const int tid  = threadIdx.x;
    const int lane = tid & 31;
    const int wid  = tid >> 5;
    const int warp_m = wid & 7;
    const int warp_n = wid >> 3;
    const int qb = (gridDim.x - 1) - blockIdx.x;
    const int bh = blockIdx.y;
    const int g    = lane >> 2;
    const int tcol = lane & 3;
    const float scale = 0.08838834764831845f;

    const float* Qg = Q  + ((size_t)bh * SEQ + qb * 128) * HD;
    const float* Kg = K  + (size_t)bh * SEQ * HD;
    const float* Vg = Vt + (size_t)bh * HD * SEQ;

    const uint32_t sbase = (uint32_t)__cvta_generic_to_shared(sm);
    const int mat = lane >> 3, r = lane & 7;
    const int a_sh = mat >> 1, a_roff = r + ((mat & 1) << 3);
    const int b_sh = mat & 1,  b_roff = r + ((mat >> 1) << 3);

    const uint32_t qa_base = sbase + (uint32_t)(warp_m * 16 + a_roff) * 512u;
    uint32_t kb_row[2];
#pragma unroll
    for (int pb = 0; pb < 2; pb++)
        kb_row[pb] = sbase + FK0 * 4 + (uint32_t)(warp_n * 32 + pb * 16 + b_roff) * 512u;
    const uint32_t pa_base = sbase + FP * 4 + (uint32_t)(warp_m * 16 + a_roff) * 256u;
    uint32_t vb_row[4];
#pragma unroll
    for (int pb = 0; pb < 4; pb++)
        vb_row[pb] = sbase + FV * 4 + (uint32_t)(warp_n * 64 + pb * 16 + b_roff) * 256u;

    const int krow = tid >> 5;
    const int kseg = tid & 31;
    const int ksw  = kseg ^ (krow & 7);
    uint32_t kdst[4];
#pragma unroll
    for (int l = 0; l < 4; l++)
        kdst[l] = sbase + (uint32_t)(FK0 + (krow + 16 * l) * 128 + ksw * 4) * 4u;

    const int vrow = tid >> 4;
    const int vseg = tid & 15;
    const int vsw  = vseg ^ (vrow & 7);
    uint32_t vdst[4];
#pragma unroll
    for (int l = 0; l < 4; l++)
        vdst[l] = sbase + (uint32_t)(FV + (vrow + 32 * l) * 64 + vsw * 4) * 4u;

    // Q tile 128x128: raw tf32 bits, swizzled
#pragma unroll
    for (int l = 0; l < 8; l++) {
        int idx = tid + l * 512;
        int row = idx >> 5;
        int seg = idx & 31;
        uint4 u = *(const uint4*)&Qg[row * HD + seg * 4];
        *(uint4*)(sm + row * 128 + (seg ^ (row & 7)) * 4) = u;
    }

    // prologue: prefetch K[0]
#pragma unroll
    for (int l = 0; l < 4; l++)
        CP_ASYNC16(kdst[l], (const void*)(Kg + (size_t)(krow + 16 * l) * HD + kseg * 4));
    CP_COMMIT();

    float o[8][4];
#pragma unroll
    for (int nf = 0; nf < 8; nf++)
#pragma unroll
        for (int c = 0; c < 4; c++) o[nf][c] = 0.f;
    float mrow[2] = {-1e30f, -1e30f};
    float lrow[2] = {0.f, 0.f};

    const int nkb = 2 * qb + 2;
    for (int kb = 0; kb < nkb; kb++) {
        const uint32_t kcur = (kb & 1) ? 32768u : 0u;

        // merged barrier: K[kb] landed; prev PV done (P/V free)
        asm volatile("cp.async.wait_group 0;");
        __syncthreads();

        // issue V[kb] and K[kb+1]
#pragma unroll
        for (int l = 0; l < 4; l++)
            CP_ASYNC16(vdst[l], (const void*)(Vg + (size_t)(vrow + 32 * l) * SEQ + kb * 64 + vseg * 4));
        CP_COMMIT();
        if (kb + 1 < nkb) {
            uint32_t koff = (kb & 1) ? 0u : 32768u;
#pragma unroll
            for (int l = 0; l < 4; l++)
                CP_ASYNC16(kdst[l] + koff,
                           (const void*)(Kg + (size_t)((kb + 1) * 64 + krow + 16 * l) * HD + kseg * 4));
        }
        CP_COMMIT();

        // scores
        float s[4][4];
#pragma unroll
        for (int nf = 0; nf < 4; nf++)
#pragma unroll
            for (int c = 0; c < 4; c++) s[nf][c] = 0.f;

#pragma unroll
        for (int ks = 0; ks < 16; ks++) {
            uint32_t a0, a1, a2, a3;
            LDSM4(a0, a1, a2, a3, qa_base + (uint32_t)((((ks << 1) + a_sh) ^ r) << 4));
            uint32_t bf[4][2];
#pragma unroll
            for (int pb = 0; pb < 2; pb++) {
                uint32_t t0, t1, t2, t3;
                LDSM4(t0, t1, t2, t3, kb_row[pb] + kcur + (uint32_t)((((ks << 1) + b_sh) ^ r) << 4));
                bf[pb * 2 + 0][0] = t0; bf[pb * 2 + 0][1] = t1;
                bf[pb * 2 + 1][0] = t2; bf[pb * 2 + 1][1] = t3;
            }
#pragma unroll
            for (int nf = 0; nf < 4; nf++)
                MMA_TF32(s[nf][0], s[nf][1], s[nf][2], s[nf][3],
                         a0, a1, a2, a3, bf[nf][0], bf[nf][1]);
        }

        // scale + causal mask
#pragma unroll
        for (int nf = 0; nf < 4; nf++)
#pragma unroll
            for (int c = 0; c < 4; c++) s[nf][c] *= scale;
        if (kb >= 2 * qb) {
#pragma unroll
            for (int nf = 0; nf < 4; nf++)
#pragma unroll
                for (int c = 0; c < 4; c++) {
                    int lr = warp_m * 16 + g + (c >> 1) * 8;
                    int lc = warp_n * 32 + nf * 8 + 2 * tcol + (c & 1);
                    if (kb * 64 + lc > qb * 128 + lr) s[nf][c] = -1e30f;
                }
        }

        // softmax
        float p[2][8], mxw[2];
#pragma unroll
        for (int h = 0; h < 2; h++) {
            float mx = s[0][h * 2];
#pragma unroll
            for (int nf = 0; nf < 4; nf++) {
                mx = fmaxf(mx, s[nf][h * 2 + 0]);
                mx = fmaxf(mx, s[nf][h * 2 + 1]);
            }
            mx = fmaxf(mx, __shfl_xor_sync(0xffffffffu, mx, 1));
            mx = fmaxf(mx, __shfl_xor_sync(0xffffffffu, mx, 2));
            float sum = 0.f;
#pragma unroll
            for (int nf = 0; nf < 4; nf++) {
                float p0 = __expf(s[nf][h * 2 + 0] - mx);
                float p1 = __expf(s[nf][h * 2 + 1] - mx);
                p[h][nf * 2 + 0] = p0;
                p[h][nf * 2 + 1] = p1;
                sum += p0 + p1;
            }
            sum += __shfl_xor_sync(0xffffffffu, sum, 1);
            sum += __shfl_xor_sync(0xffffffffu, sum, 2);
            mxw[h] = mx;
            if (tcol == 0)
                redp[(warp_m * 16 + g + h * 8) * 2 + warp_n] = make_float2(mx, sum);
        }
        __syncthreads();

#pragma unroll
        for (int h = 0; h < 2; h++) {
            int row = warp_m * 16 + g + h * 8;
            float2 e0 = redp[row * 2 + 0];
            float2 e1 = redp[row * 2 + 1];
            float mnew  = fmaxf(mrow[h], fmaxf(e0.x, e1.x));
            float alpha = __expf(mrow[h] - mnew);
            lrow[h] = lrow[h] * alpha + e0.y * __expf(e0.x - mnew)
                                      + e1.y * __expf(e1.x - mnew);
            mrow[h] = mnew;
            float fac = __expf(mxw[h] - mnew);
#pragma unroll
            for (int nf = 0; nf < 4; nf++) {
                int col = warp_n * 32 + nf * 8 + 2 * tcol;
                uint32_t w = FP + row * 64 + ((col >> 2) ^ (row & 7)) * 4 + (col & 3);
                uint2 u = make_uint2(f2tf(p[h][nf * 2 + 0] * fac),
                                     f2tf(p[h][nf * 2 + 1] * fac));
                *(uint2*)(sm + w) = u;
            }
#pragma unroll
            for (int nfo = 0; nfo < 8; nfo++) {
                o[nfo][h * 2 + 0] *= alpha;
                o[nfo][h * 2 + 1] *= alpha;
            }
        }

        asm volatile("cp.async.wait_group 1;");   // V[kb] landed (K[kb+1] pending)
        __syncthreads();                          // P + V visible

        // PV
#pragma unroll
        for (int ks = 0; ks < 8; ks++) {
            uint32_t a0, a1, a2, a3;
            LDSM4(a0, a1, a2, a3, pa_base + (uint32_t)((((ks << 1) + a_sh) ^ r) << 4));
            uint32_t bf[8][2];
#pragma unroll
            for (int pb = 0; pb < 4; pb++) {
                uint32_t t0, t1, t2, t3;
                LDSM4(t0, t1, t2, t3, vb_row[pb] + (uint32_t)((((ks << 1) + b_sh) ^ r) << 4));
                bf[pb * 2 + 0][0] = t0; bf[pb * 2 + 0][1] = t1;
                bf[pb * 2 + 1][0] = t2; bf[pb * 2 + 1][1] = t3;
            }
#pragma unroll
            for (int nf = 0; nf < 8; nf++)
                MMA_TF32(o[nf][0], o[nf][1], o[nf][2], o[nf][3],
                         a0, a1, a2, a3, bf[nf][0], bf[nf][1]);
        }
    }

    // epilogue
    const int b = bh >> 4;
    const int hh = bh & 15;
#pragma unroll
    for (int h = 0; h < 2; h++) {
        float inv = 1.0f / lrow[h];
        int srow = qb * 128 + warp_m * 16 + g + h * 8;
        float* op = Out + ((size_t)(b * SEQ + srow)) * HIDDEN + hh * HD;
#pragma unroll
        for (int nf = 0; nf < 8; nf++) {
            int d = warp_n * 64 + nf * 8 + 2 * tcol;
            uint2 u = make_uint2(f2tf(o[nf][h * 2 + 0] * inv),
                                 f2tf(o[nf][h * 2 + 1] * inv));
            *(uint2*)(op + d) = u;
        }
    }
}

// =======================================================================
extern "C" void kernel_launch(void* const* d_in, const int* in_sizes, int n_in,
                              void* d_out, int out_size)
{
    const float* x  = (const float*)d_in[0];
    const float* wq = (const float*)d_in[1];
    const float* bq = (const float*)d_in[2];
    const float* wk = (const float*)d_in[3];
    const float* bk = (const float*)d_in[4];
    const float* wv = (const float*)d_in[5];
    const float* bv = (const float*)d_in[6];
    const float* wo = (const float*)d_in[7];
    const float* bo = (const float*)d_in[8];
    float* out = (float*)d_out;

    float *xt, *tw, *two, *q, *k, *v, *vt, *a;
    cudaGetSymbolAddress((void**)&xt,  g_xt);
    cudaGetSymbolAddress((void**)&tw,  g_tw);
    cudaGetSymbolAddress((void**)&two, g_two);
    cudaGetSymbolAddress((void**)&q,   g_q);
    cudaGetSymbolAddress((void**)&k,   g_k);
    cudaGetSymbolAddress((void**)&v,   g_v);
    cudaGetSymbolAddress((void**)&vt,  g_vt);
    cudaGetSymbolAddress((void**)&a,   g_a);

    static int attr_done = 0;
    if (!attr_done) {
        cudaFuncSetAttribute(gemm_cp, cudaFuncAttributeMaxDynamicSharedMemorySize, GEMM_SMEM);
        cudaFuncSetAttribute(flash_tf32, cudaFuncAttributeMaxDynamicSharedMemorySize, FLASH_SMEM);
        attr_done = 1;
    }

    // tf32 pre-round (single launch, one balanced wave: 148 SMs x 8 CTAs)
    cvt_all<<<1184, 256>>>(xt, x, tw, wq, wk, wv, two, wo);

    // fused QKV projection: N = 6144
    gemm_cp<<<dim3(3 * HIDDEN / 128, MTOT / 128), 256, GEMM_SMEM>>>(
        xt, tw, bq, bk, bv, q, k, v, MTOT, 3 * HIDDEN, HIDDEN, 1);

    transpose_v<<<dim3(HD / 32, SEQ / 32, BATCH * NH), 256>>>(v, vt);

    flash_tf32<<<dim3(SEQ / 128, BATCH * NH), 512, FLASH_SMEM>>>(q, k, vt, a);

    // output projection (full fp32 out)
    gemm_cp<<<dim3(HIDDEN / 128, MTOT / 128), 256, GEMM_SMEM>>>(
        a, two, bo, bo, bo, out, out, out, MTOT, HIDDEN, HIDDEN, 0);
}

// round 16
// speedup vs baseline: 2.5394x; 1.6304x over previous
#include <cuda_runtime.h>
#include <cuda_fp16.h>
#include <math.h>
#include <stdint.h>

#define HIDDEN 2048
#define NH 16
#define HD 128
#define SEQ 2048
#define BATCH 2
#define MTOT (BATCH*SEQ)   /* 4096 */

// ---------------- scratch (static device memory; no allocation) ----------------
__device__ __half g_xt [(size_t)MTOT * HIDDEN];        // x, fp16
__device__ __half g_tw [(size_t)3 * HIDDEN * HIDDEN];  // wq|wk|wv packed, fp16
__device__ __half g_two[(size_t)HIDDEN * HIDDEN];      // wo, fp16
__device__ __half g_q  [(size_t)MTOT * HIDDEN];        // [B,nh,S,hd] fp16
__device__ __half g_k  [(size_t)MTOT * HIDDEN];        // [B,nh,S,hd] fp16
__device__ __half g_v  [(size_t)MTOT * HIDDEN];        // [B,nh,S,hd] fp16
__device__ __half g_vt [(size_t)MTOT * HIDDEN];        // [B,nh,hd,S] fp16
__device__ __half g_a  [(size_t)MTOT * HIDDEN];        // [B,S,H] fp16

#define LDSM4(R0,R1,R2,R3,ADDR) \
    asm volatile("ldmatrix.sync.aligned.m8n8.x4.shared.b16 {%0,%1,%2,%3}, [%4];" \
                 : "=r"(R0),"=r"(R1),"=r"(R2),"=r"(R3) : "r"(ADDR))

#define MMA_F16(C0,C1,C2,C3,A0,A1,A2,A3,B0,B1) \
    asm volatile("mma.sync.aligned.m16n8k16.row.col.f32.f16.f16.f32 " \
                 "{%0,%1,%2,%3},{%4,%5,%6,%7},{%8,%9},{%0,%1,%2,%3};" \
                 : "+f"(C0),"+f"(C1),"+f"(C2),"+f"(C3) \
                 : "r"(A0),"r"(A1),"r"(A2),"r"(A3),"r"(B0),"r"(B1))

#define CP_ASYNC16(SA, GA) \
    asm volatile("cp.async.cg.shared.global [%0], [%1], 16;" :: "r"(SA), "l"(GA))
#define CP_COMMIT() asm volatile("cp.async.commit_group;")

__device__ __forceinline__ uint32_t h2_bits(float a, float b) {
    __half2 h = __floats2half2_rn(a, b);
    return *(uint32_t*)&h;
}

// =======================================================================
// Single-pass fp16 conversion of x, wq|wk|wv (packed), wo
// =======================================================================
#define NX4 (MTOT * HIDDEN / 4)
#define NW4 (HIDDEN * HIDDEN / 4)
#define NTOT4 (NX4 + 4 * NW4)

__global__ __launch_bounds__(256)
void cvt_all(__half* __restrict__ xt, const float* __restrict__ x,
             __half* __restrict__ tw, const float* __restrict__ wq,
             const float* __restrict__ wk, const float* __restrict__ wv,
             __half* __restrict__ two, const float* __restrict__ wo)
{
    int i = blockIdx.x * blockDim.x + threadIdx.x;
    int stride = gridDim.x * blockDim.x;
    for (; i < NTOT4; i += stride) {
        const float4* sp;
        __half* dp;
        if (i < NX4) {
            sp = (const float4*)x + i;            dp = xt + (size_t)i * 4;
        } else {
            int j = i - NX4;
            int w = j / NW4, off = j - w * NW4;
            if      (w == 0) { sp = (const float4*)wq + off; dp = tw + (size_t)off * 4; }
            else if (w == 1) { sp = (const float4*)wk + off; dp = tw + (size_t)HIDDEN*HIDDEN + (size_t)off * 4; }
            else if (w == 2) { sp = (const float4*)wv + off; dp = tw + (size_t)2*HIDDEN*HIDDEN + (size_t)off * 4; }
            else             { sp = (const float4*)wo + off; dp = two + (size_t)off * 4; }
        }
        float4 v = *sp;
        uint2 u = make_uint2(h2_bits(v.x, v.y), h2_bits(v.z, v.w));
        *(uint2*)dp = u;
    }
}

// =======================================================================
// cp.async 3-stage fp16 GEMM (NT), BM=128, BN=128, BK=64, 256 threads
// + L2-friendly CTA swizzle. Same addressing as proven tf32 kernel
// (128B smem rows), mma = m16n8k16.
// =======================================================================
#define STAGES 3
#define STG_U32 8192
#define GEMM_SMEM (STAGES*STG_U32*4)      /* 98304 B -> 2 CTAs/SM */

__global__ __launch_bounds__(256)
void gemm_cp(const __half* __restrict__ A, const __half* __restrict__ W,
             const float* __restrict__ b0, const float* __restrict__ b1,
             const float* __restrict__ b2,
             void* __restrict__ C0v, void* __restrict__ C1v, void* __restrict__ C2v,
             int M, int N, int K, int mode)
{
    extern __shared__ uint32_t smem_u[];
    const int tid  = threadIdx.x;
    const int lane = tid & 31;
    const int wid  = tid >> 5;
    const int warp_m = wid >> 2;
    const int warp_n = wid & 3;

    int bid   = blockIdx.y * gridDim.x + blockIdx.x;
    int chunk = gridDim.x * 8;
    int cid   = bid / chunk;
    int rem   = bid - cid * chunk;
    int by    = cid * 8 + (rem & 7);
    int bx    = rem >> 3;
    const int m0 = by * 128;
    const int n0 = bx * 128;

    const int mat = lane >> 3, r = lane & 7;
    const int a_sh = mat >> 1, a_roff = r + ((mat & 1) << 3);
    const int b_sh = mat & 1,  b_roff = r + ((mat >> 1) << 3);

    const int grow = tid >> 3;
    const int gseg = tid & 7;
    const int sseg = gseg ^ (grow & 7);

    const uint32_t sbase = (uint32_t)__cvta_generic_to_shared(smem_u);

    uint32_t sa[4], sb[4];
#pragma unroll
    for (int l = 0; l < 4; l++) {
        sa[l] = sbase + (uint32_t)((grow + 32 * l) * 32 + sseg * 4) * 4u;
        sb[l] = sa[l] + 16384u;
    }

    uint32_t rowbA[4], rowbB[2];
#pragma unroll
    for (int mf = 0; mf < 4; mf++)
        rowbA[mf] = (uint32_t)(warp_m * 64 + mf * 16 + a_roff) * 128u;
#pragma unroll
    for (int pb = 0; pb < 2; pb++)
        rowbB[pb] = (uint32_t)(warp_n * 32 + pb * 16 + b_roff) * 128u + 16384u;

    float acc[4][4][4];
#pragma unroll
    for (int i = 0; i < 4; i++)
#pragma unroll
        for (int j = 0; j < 4; j++)
#pragma unroll
            for (int c = 0; c < 4; c++) acc[i][j][c] = 0.f;

    const int KT = K >> 6;   /* BK = 64 halves = 128B rows */

#pragma unroll
    for (int s = 0; s < STAGES - 1; s++) {
        int k0 = s * 64;
        uint32_t soff = (uint32_t)s * 32768u;
#pragma unroll
        for (int l = 0; l < 4; l++) {
            int row = grow + 32 * l;
            CP_ASYNC16(sa[l] + soff, (const void*)(A + (size_t)(m0 + row) * K + k0 + gseg * 8));
            CP_ASYNC16(sb[l] + soff, (const void*)(W + (size_t)(n0 + row) * K + k0 + gseg * 8));
        }
        CP_COMMIT();
    }

    int stage = 0;
    for (int kt = 0; kt < KT; kt++) {
        asm volatile("cp.async.wait_group 1;");
        __syncthreads();

        const uint32_t abase = sbase + (uint32_t)stage * 32768u;
#pragma unroll
        for (int ks = 0; ks < 4; ks++) {
            uint32_t af[4][4];
            uint32_t bf[4][2];
#pragma unroll
            for (int mf = 0; mf < 4; mf++) {
                uint32_t addr = abase + rowbA[mf] + (uint32_t)((((ks << 1) + a_sh) ^ r) << 4);
                LDSM4(af[mf][0], af[mf][1], af[mf][2], af[mf][3], addr);
            }
#pragma unroll
            for (int pb = 0; pb < 2; pb++) {
                uint32_t addr = abase + rowbB[pb] + (uint32_t)((((ks << 1) + b_sh) ^ r) << 4);
                uint32_t t0, t1, t2, t3;
                LDSM4(t0, t1, t2, t3, addr);
                bf[pb * 2 + 0][0] = t0; bf[pb * 2 + 0][1] = t1;
                bf[pb * 2 + 1][0] = t2; bf[pb * 2 + 1][1] = t3;
            }
#pragma unroll
            for (int mf = 0; mf < 4; mf++)
#pragma unroll
                for (int nf = 0; nf < 4; nf++)
                    MMA_F16(acc[mf][nf][0], acc[mf][nf][1], acc[mf][nf][2], acc[mf][nf][3],
                            af[mf][0], af[mf][1], af[mf][2], af[mf][3],
                            bf[nf][0], bf[nf][1]);
        }

        int kn = kt + STAGES - 1;
        if (kn < KT) {
            int k0 = kn * 64;
            uint32_t soff = (uint32_t)(kn % STAGES) * 32768u;
#pragma unroll
            for (int l = 0; l < 4; l++) {
                int row = grow + 32 * l;
                CP_ASYNC16(sa[l] + soff, (const void*)(A + (size_t)(m0 + row) * K + k0 + gseg * 8));
                CP_ASYNC16(sb[l] + soff, (const void*)(W + (size_t)(n0 + row) * K + k0 + gseg * 8));
            }
        }
        CP_COMMIT();
        stage = (stage + 1 == STAGES) ? 0 : stage + 1;
    }

    const int group = lane >> 2;
    const int tcol  = lane & 3;
    const int which = n0 >> 11;
    const float* bp = (which == 0) ? b0 : (which == 1) ? b1 : b2;
    void* Cwv = (which == 0) ? C0v : (which == 1) ? C1v : C2v;

#pragma unroll
    for (int mf = 0; mf < 4; mf++) {
#pragma unroll
        for (int nf = 0; nf < 4; nf++) {
            int col = n0 + warp_n * 32 + nf * 8 + tcol * 2;
            int colr = col & 2047;
            float bb0, bb1;
            if (mode) { bb0 = bp[colr]; bb1 = bp[colr + 1]; }
            else      { bb0 = b0[col];  bb1 = b0[col + 1]; }
            int mrow0 = m0 + warp_m * 64 + mf * 16 + group;
#pragma unroll
            for (int half = 0; half < 2; half++) {
                int mrow = mrow0 + half * 8;
                float v0 = acc[mf][nf][half * 2 + 0] + bb0;
                float v1 = acc[mf][nf][half * 2 + 1] + bb1;
                if (!mode) {
                    *(float2*)((float*)C0v + (size_t)mrow * N + col) = make_float2(v0, v1);
                } else {
                    int b = mrow >> 11;
                    int s = mrow & 2047;
                    int h = colr >> 7;
                    int d = colr & 127;
                    uint32_t u = h2_bits(v0, v1);
                    *(uint32_t*)((__half*)Cwv + (((size_t)((b << 4) + h) * SEQ + s) << 7) + d) = u;
                }
            }
        }
    }
}

// =======================================================================
// V transpose (fp16): [bh][s][d] -> [bh][d][s]
// =======================================================================
__global__ __launch_bounds__(256)
void transpose_v(const __half* __restrict__ in, __half* __restrict__ out)
{
    __shared__ __half t[32][33];
    const int bh = blockIdx.z;
    const int d0 = blockIdx.x * 32;
    const int s0 = blockIdx.y * 32;
    const __half* ip = in  + (size_t)bh * SEQ * HD;
    __half*       op = out + (size_t)bh * HD * SEQ;
    const int tx = threadIdx.x & 31;
    const int ty = threadIdx.x >> 5;
#pragma unroll
    for (int j = 0; j < 32; j += 8)
        t[ty + j][tx] = ip[(size_t)(s0 + ty + j) * HD + d0 + tx];
    __syncthreads();
#pragma unroll
    for (int j = 0; j < 32; j += 8)
        op[(size_t)(d0 + ty + j) * SEQ + s0 + tx] = t[tx][ty + j];
}

// =======================================================================
// fp16 flash attention (R12 schedule): Br=128, Bc=64, 512 threads,
// K double-buffered cp.async, V issued post-K-sync, 3 barriers/iter.
// Smem u32: Q[8192] K0[4096] K1[4096] V[4096] P[4096] red[512]
// Q/K rows 256B, V/P rows 128B; swizzle c^r (XOR touches low 3 bits only).
// =======================================================================
#define FQ   0
#define FK0  8192
#define FV   16384
#define FP   20480
#define FRED 24576
#define FLASH_SMEM ((24576 + 512) * 4)   /* 100352 B */

__global__ __launch_bounds__(512)
void flash_f16(const __half* __restrict__ Q, const __half* __restrict__ K,
               const __half* __restrict__ Vt, __half* __restrict__ Out)
{
    extern __shared__ uint32_t sm[];
    float2* redp = (float2*)(sm + FRED);

    const int tid  = threadIdx.x;
    const int lane = tid & 31;
    const int wid  = tid >> 5;
    const int warp_m = wid & 7;
    const int warp_n = wid >> 3;
    const int qb = (gridDim.x - 1) - blockIdx.x;
    const int bh = blockIdx.y;
    const int g    = lane >> 2;
    const int tcol = lane & 3;
    const float scale = 0.08838834764831845f;

    const __half* Qg = Q  + ((size_t)bh * SEQ + qb * 128) * HD;
    const __half* Kg = K  + (size_t)bh * SEQ * HD;
    const __half* Vg = Vt + (size_t)bh * HD * SEQ;

    const uint32_t sbase = (uint32_t)__cvta_generic_to_shared(sm);
    const int mat = lane >> 3, r = lane & 7;
    const int a_sh = mat >> 1, a_roff = r + ((mat & 1) << 3);
    const int b_sh = mat & 1,  b_roff = r + ((mat >> 1) << 3);

    const uint32_t qa_base = sbase + (uint32_t)(warp_m * 16 + a_roff) * 256u;
    uint32_t kb_row[2];
#pragma unroll
    for (int pb = 0; pb < 2; pb++)
        kb_row[pb] = sbase + FK0 * 4 + (uint32_t)(warp_n * 32 + pb * 16 + b_roff) * 256u;
    const uint32_t pa_base = sbase + FP * 4 + (uint32_t)(warp_m * 16 + a_roff) * 128u;
    uint32_t vb_row[4];
#pragma unroll
    for (int pb = 0; pb < 4; pb++)
        vb_row[pb] = sbase + FV * 4 + (uint32_t)(warp_n * 64 + pb * 16 + b_roff) * 128u;

    // K cp.async: 64 rows x 16 segs of 16B (row = 256B)
    const int krow = tid >> 4;          // 0..31, +32*l
    const int kseg = tid & 15;
    const int ksw  = kseg ^ (krow & 7); // row&7 invariant across l (32l%8==0)
    uint32_t kdst[2];
#pragma unroll
    for (int l = 0; l < 2; l++)
        kdst[l] = sbase + (uint32_t)(FK0 + (krow + 32 * l) * 64 + ksw * 4) * 4u;

    // V cp.async: 128 d-rows x 8 segs of 16B (row = 128B)
    const int vrow = tid >> 3;          // 0..63, +64*l
    const int vseg = tid & 7;
    const int vsw  = vseg ^ (vrow & 7); // row&7 invariant across l
    uint32_t vdst[2];
#pragma unroll
    for (int l = 0; l < 2; l++)
        vdst[l] = sbase + (uint32_t)(FV + (vrow + 64 * l) * 32 + vsw * 4) * 4u;

    // Q tile 128x128 halves: 128 rows x 16 segs, swizzled
#pragma unroll
    for (int l = 0; l < 4; l++) {
        int idx = tid + l * 512;
        int row = idx >> 4;
        int seg = idx & 15;
        uint4 u = *(const uint4*)(Qg + row * HD + seg * 8);
        *(uint4*)(sm + row * 64 + (seg ^ (row & 7)) * 4) = u;
    }

    // prologue: prefetch K[0]
#pragma unroll
    for (int l = 0; l < 2; l++)
        CP_ASYNC16(kdst[l], (const void*)(Kg + (size_t)(krow + 32 * l) * HD + kseg * 8));
    CP_COMMIT();

    float o[8][4];
#pragma unroll
    for (int nf = 0; nf < 8; nf++)
#pragma unroll
        for (int c = 0; c < 4; c++) o[nf][c] = 0.f;
    float mrow[2] = {-1e30f, -1e30f};
    float lrow[2] = {0.f, 0.f};

    const int nkb = 2 * qb + 2;
    for (int kb = 0; kb < nkb; kb++) {
        const uint32_t kcur = (kb & 1) ? 16384u : 0u;

        // merged barrier: K[kb] landed; prev PV done
        asm volatile("cp.async.wait_group 0;");
        __syncthreads();

        // issue V[kb] and K[kb+1]
#pragma unroll
        for (int l = 0; l < 2; l++)
            CP_ASYNC16(vdst[l], (const void*)(Vg + (size_t)(vrow + 64 * l) * SEQ + kb * 64 + vseg * 8));
        CP_COMMIT();
        if (kb + 1 < nkb) {
            uint32_t koff = (kb & 1) ? 0u : 16384u;
#pragma unroll
            for (int l = 0; l < 2; l++)
                CP_ASYNC16(kdst[l] + koff,
                           (const void*)(Kg + (size_t)((kb + 1) * 64 + krow + 32 * l) * HD + kseg * 8));
        }
        CP_COMMIT();

        // scores: 8 k16-steps over hd=128
        float s[4][4];
#pragma unroll
        for (int nf = 0; nf < 4; nf++)
#pragma unroll
            for (int c = 0; c < 4; c++) s[nf][c] = 0.f;

#pragma unroll
        for (int ks = 0; ks < 8; ks++) {
            uint32_t a0, a1, a2, a3;
            LDSM4(a0, a1, a2, a3, qa_base + (uint32_t)((((ks << 1) + a_sh) ^ r) << 4));
            uint32_t bf[4][2];
#pragma unroll
            for (int pb = 0; pb < 2; pb++) {
                uint32_t t0, t1, t2, t3;
                LDSM4(t0, t1, t2, t3, kb_row[pb] + kcur + (uint32_t)((((ks << 1) + b_sh) ^ r) << 4));
                bf[pb * 2 + 0][0] = t0; bf[pb * 2 + 0][1] = t1;
                bf[pb * 2 + 1][0] = t2; bf[pb * 2 + 1][1] = t3;
            }
#pragma unroll
            for (int nf = 0; nf < 4; nf++)
                MMA_F16(s[nf][0], s[nf][1], s[nf][2], s[nf][3],
                        a0, a1, a2, a3, bf[nf][0], bf[nf][1]);
        }

        // scale + causal mask
#pragma unroll
        for (int nf = 0; nf < 4; nf++)
#pragma unroll
            for (int c = 0; c < 4; c++) s[nf][c] *= scale;
        if (kb >= 2 * qb) {
#pragma unroll
            for (int nf = 0; nf < 4; nf++)
#pragma unroll
                for (int c = 0; c < 4; c++) {
                    int lr = warp_m * 16 + g + (c >> 1) * 8;
                    int lc = warp_n * 32 + nf * 8 + 2 * tcol + (c & 1);
                    if (kb * 64 + lc > qb * 128 + lr) s[nf][c] = -1e30f;
                }
        }

        // softmax
        float p[2][8], mxw[2];
#pragma unroll
        for (int h = 0; h < 2; h++) {
            float mx = s[0][h * 2];
#pragma unroll
            for (int nf = 0; nf < 4; nf++) {
                mx = fmaxf(mx, s[nf][h * 2 + 0]);
                mx = fmaxf(mx, s[nf][h * 2 + 1]);
            }
            mx = fmaxf(mx, __shfl_xor_sync(0xffffffffu, mx, 1));
            mx = fmaxf(mx, __shfl_xor_sync(0xffffffffu, mx, 2));
            float sum = 0.f;
#pragma unroll
            for (int nf = 0; nf < 4; nf++) {
                float p0 = __expf(s[nf][h * 2 + 0] - mx);
                float p1 = __expf(s[nf][h * 2 + 1] - mx);
                p[h][nf * 2 + 0] = p0;
                p[h][nf * 2 + 1] = p1;
                sum += p0 + p1;
            }
            sum += __shfl_xor_sync(0xffffffffu, sum, 1);
            sum += __shfl_xor_sync(0xffffffffu, sum, 2);
            mxw[h] = mx;
            if (tcol == 0)
                redp[(warp_m * 16 + g + h * 8) * 2 + warp_n] = make_float2(mx, sum);
        }
        __syncthreads();

#pragma unroll
        for (int h = 0; h < 2; h++) {
            int row = warp_m * 16 + g + h * 8;
            float2 e0 = redp[row * 2 + 0];
            float2 e1 = redp[row * 2 + 1];
            float mnew  = fmaxf(mrow[h], fmaxf(e0.x, e1.x));
            float alpha = __expf(mrow[h] - mnew);
            lrow[h] = lrow[h] * alpha + e0.y * __expf(e0.x - mnew)
                                      + e1.y * __expf(e1.x - mnew);
            mrow[h] = mnew;
            float fac = __expf(mxw[h] - mnew);
            // store P (fp16 pairs) with swizzle: row=128B, word tcol of chunk col>>3
#pragma unroll
            for (int nf = 0; nf < 4; nf++) {
                int col = warp_n * 32 + nf * 8 + 2 * tcol;
                uint32_t w = FP + row * 32 + (((col >> 3) ^ (row & 7)) << 2) + tcol;
                sm[w] = h2_bits(p[h][nf * 2 + 0] * fac, p[h][nf * 2 + 1] * fac);
            }
#pragma unroll
            for (int nfo = 0; nfo < 8; nfo++) {
                o[nfo][h * 2 + 0] *= alpha;
                o[nfo][h * 2 + 1] *= alpha;
            }
        }

        asm volatile("cp.async.wait_group 1;");   // V[kb] landed
        __syncthreads();                          // P + V visible

        // PV: 4 k16-steps over j=64
#pragma unroll
        for (int ks = 0; ks < 4; ks++) {
            uint32_t a0, a1, a2, a3;
            LDSM4(a0, a1, a2, a3, pa_base + (uint32_t)((((ks << 1) + a_sh) ^ r) << 4));
            uint32_t bf[8][2];
#pragma unroll
            for (int pb = 0; pb < 4; pb++) {
                uint32_t t0, t1, t2, t3;
                LDSM4(t0, t1, t2, t3, vb_row[pb] + (uint32_t)((((ks << 1) + b_sh) ^ r) << 4));
                bf[pb * 2 + 0][0] = t0; bf[pb * 2 + 0][1] = t1;
                bf[pb * 2 + 1][0] = t2; bf[pb * 2 + 1][1] = t3;
            }
#pragma unroll
            for (int nf = 0; nf < 8; nf++)
                MMA_F16(o[nf][0], o[nf][1], o[nf][2], o[nf][3],
                        a0, a1, a2, a3, bf[nf][0], bf[nf][1]);
        }
    }

    // epilogue: normalize, fp16, store merged-heads [B,S,H]
    const int b = bh >> 4;
    const int hh = bh & 15;
#pragma unroll
    for (int h = 0; h < 2; h++) {
        float inv = 1.0f / lrow[h];
        int srow = qb * 128 + warp_m * 16 + g + h * 8;
        __half* op = Out + ((size_t)(b * SEQ + srow)) * HIDDEN + hh * HD;
#pragma unroll
        for (int nf = 0; nf < 8; nf++) {
            int d = warp_n * 64 + nf * 8 + 2 * tcol;
            *(uint32_t*)(op + d) = h2_bits(o[nf][h * 2 + 0] * inv, o[nf][h * 2 + 1] * inv);
        }
    }
}

// =======================================================================
extern "C" void kernel_launch(void* const* d_in, const int* in_sizes, int n_in,
                              void* d_out, int out_size)
{
    const float* x  = (const float*)d_in[0];
    const float* wq = (const float*)d_in[1];
    const float* bq = (const float*)d_in[2];
    const float* wk = (const float*)d_in[3];
    const float* bk = (const float*)d_in[4];
    const float* wv = (const float*)d_in[5];
    const float* bv = (const float*)d_in[6];
    const float* wo = (const float*)d_in[7];
    const float* bo = (const float*)d_in[8];
    float* out = (float*)d_out;

    __half *xt, *tw, *two, *q, *k, *v, *vt, *a;
    cudaGetSymbolAddress((void**)&xt,  g_xt);
    cudaGetSymbolAddress((void**)&tw,  g_tw);
    cudaGetSymbolAddress((void**)&two, g_two);
    cudaGetSymbolAddress((void**)&q,   g_q);
    cudaGetSymbolAddress((void**)&k,   g_k);
    cudaGetSymbolAddress((void**)&v,   g_v);
    cudaGetSymbolAddress((void**)&vt,  g_vt);
    cudaGetSymbolAddress((void**)&a,   g_a);

    static int attr_done = 0;
    if (!attr_done) {
        cudaFuncSetAttribute(gemm_cp, cudaFuncAttributeMaxDynamicSharedMemorySize, GEMM_SMEM);
        cudaFuncSetAttribute(flash_f16, cudaFuncAttributeMaxDynamicSharedMemorySize, FLASH_SMEM);
        attr_done = 1;
    }

    // fp16 conversion (single launch, one balanced wave)
    cvt_all<<<1184, 256>>>(xt, x, tw, wq, wk, wv, two, wo);

    // fused QKV projection: N = 6144
    gemm_cp<<<dim3(3 * HIDDEN / 128, MTOT / 128), 256, GEMM_SMEM>>>(
        xt, tw, bq, bk, bv, q, k, v, MTOT, 3 * HIDDEN, HIDDEN, 1);

    transpose_v<<<dim3(HD / 32, SEQ / 32, BATCH * NH), 256>>>(v, vt);

    flash_f16<<<dim3(SEQ / 128, BATCH * NH), 512, FLASH_SMEM>>>(q, k, vt, a);

    // output projection (fp32 out)
    gemm_cp<<<dim3(HIDDEN / 128, MTOT / 128), 256, GEMM_SMEM>>>(
        a, two, bo, bo, bo, out, out, out, MTOT, HIDDEN, HIDDEN, 0);
}